// round 13
// baseline (speedup 1.0000x reference)
#include <cuda_runtime.h>
#include <cuda_bf16.h>
#include <math.h>
#include <stdint.h>

#define N_NODES   50000
#define N_GROUPS  10000
#define N_EDGES   500000
#define N_TRIP    1000000
#define HID       128
#define EPSF      1e-6f
#define CUTOFF    5.0f
#define PI_F      3.14159265358979323846f

#define SBF_STRIDE 44                  // 42 used + 2 pad -> 176B rows (16B aligned)
#define TILE_M    32
#define N_TILES   (N_EDGES / TILE_M)   // 15625 exact
#define APAD      25                   // smem A plane row stride (u32)

// sbf accumulators (zeroed by memset each call); compact rbf rows (12 MB, L2-resident)
__device__ __align__(16) float g_sbf[(size_t)N_EDGES * SBF_STRIDE];
__device__ __align__(16) float g_rbf[(size_t)N_EDGES * 6];
__device__ unsigned char g_active[N_EDGES];   // envelope-nonzero flag per edge
// W split planes, packed as bf16x2 pairs in B-fragment order: Wp[k/2][h]
__device__ uint32_t g_Wp_hi[24 * HID];
__device__ uint32_t g_Wp_lo[24 * HID];

// ===========================================================================
// Kernel 1: per-edge RBF -> compact g_rbf + active flag
// ===========================================================================
__global__ void rbf_kernel(const float* __restrict__ node_pos,
                           const int*   __restrict__ edge_i,
                           const int*   __restrict__ edge_j)
{
    int e = blockIdx.x * blockDim.x + threadIdx.x;
    if (e >= N_EDGES) return;
    int i = edge_i[e], j = edge_j[e];
    float dx = node_pos[3*i+0] - node_pos[3*j+0];
    float dy = node_pos[3*i+1] - node_pos[3*j+1];
    float dz = node_pos[3*i+2] - node_pos[3*j+2];
    float d  = sqrtf(dx*dx + dy*dy + dz*dz);
    d = fmaxf(d, EPSF);
    float ds = d / CUTOFF;

    float r0=0.f,r1=0.f,r2=0.f,r3=0.f,r4=0.f,r5=0.f;
    bool act = (ds <= 1.0f);
    if (act) {
        float th = PI_F * ds;
        float s, c;
        sincosf(th, &s, &c);
        float env = 0.5f * (c + 1.0f);
        float inv = env / fmaxf(ds, 1e-6f);
        float c2 = 2.0f * c;
        float sm2 = 0.0f, sm1 = s, sn;
        r0 = inv * sm1;
        sn = c2*sm1 - sm2; sm2 = sm1; sm1 = sn; r1 = inv * sn;
        sn = c2*sm1 - sm2; sm2 = sm1; sm1 = sn; r2 = inv * sn;
        sn = c2*sm1 - sm2; sm2 = sm1; sm1 = sn; r3 = inv * sn;
        sn = c2*sm1 - sm2; sm2 = sm1; sm1 = sn; r4 = inv * sn;
        sn = c2*sm1 - sm2; sm2 = sm1; sm1 = sn; r5 = inv * sn;
    }
    float* row = g_rbf + (size_t)e * 6;
    *(float2*)(row + 0) = make_float2(r0, r1);
    *(float2*)(row + 2) = make_float2(r2, r3);
    *(float2*)(row + 4) = make_float2(r4, r5);
    g_active[e] = act ? 1 : 0;
}

// ===========================================================================
// Kernel 2: triplet features. cos(theta) algebraically:
//   cos(atan2(y,x)) = x/sqrt(x^2+y^2);  cos(6t) = T6(cos t).
// 1-byte active-flag test first (L2-resident 500KB map); flag==0 iff the
// entire rbf row is exactly zero -> contribution is exactly 0.
// ===========================================================================
__global__ void triplet_kernel(const float* __restrict__ node_pos,
                               const float* __restrict__ group_pos,
                               const int* __restrict__ t_i,
                               const int* __restrict__ t_j,
                               const int* __restrict__ t_k,
                               const int* __restrict__ id_kj,
                               const int* __restrict__ id_ji)
{
    int t = blockIdx.x * blockDim.x + threadIdx.x;
    if (t >= N_TRIP) return;

    int kj = id_kj[t];
    if (!__ldg(&g_active[kj])) return;

    const float* rrow = g_rbf + (size_t)kj * 6;
    float2 ra  = __ldg((const float2*)(rrow + 0));
    float2 rbp = __ldg((const float2*)(rrow + 2));
    float2 rc  = __ldg((const float2*)(rrow + 4));

    int ti = t_i[t], tj = t_j[t], tk = t_k[t];
    float gx = group_pos[3*ti+0], gy = group_pos[3*ti+1], gz = group_pos[3*ti+2];
    float ax = node_pos[3*tj+0] - gx, ay = node_pos[3*tj+1] - gy, az = node_pos[3*tj+2] - gz;
    float bx = node_pos[3*tk+0] - gx, by = node_pos[3*tk+1] - gy, bz = node_pos[3*tk+2] - gz;

    float n1 = sqrtf(ax*ax + ay*ay + az*az) + EPSF;
    float n2 = sqrtf(bx*bx + by*by + bz*bz) + EPSF;
    bool too_close = (n1 < 1e-4f) || (n2 < 1e-4f);
    float i1 = __fdividef(1.0f, n1), i2 = __fdividef(1.0f, n2);
    float ux = ax*i1, uy = ay*i1, uz = az*i1;
    float vx = bx*i2, vy = by*i2, vz = bz*i2;
    float x = ux*vx + uy*vy + uz*vz;
    x = fminf(fmaxf(x, -1.0f + EPSF), 1.0f - EPSF);
    float cx_ = uy*vz - uz*vy;
    float cy_ = uz*vx - ux*vz;
    float cz_ = ux*vy - uy*vx;
    float y2 = cx_*cx_ + cy_*cy_ + cz_*cz_;
    float c = too_close ? 0.0f : x * rsqrtf(x*x + y2);

    float c2 = c*c, c3 = c2*c, c4 = c2*c2, c5 = c3*c2, c6 = c3*c3;
    float cb[7];
    cb[0] = 0.2820947917738781f;
    cb[1] = 0.4886025119029199f * c;
    cb[2] = 0.6307831305050401f * (1.5f*c2 - 0.5f);
    cb[3] = 0.7463526651802308f * (2.5f*c3 - 1.5f*c);
    cb[4] = 0.8462843753216345f * (4.375f*c4 - 3.75f*c2 + 0.375f);
    cb[5] = 0.9356025796273889f * (7.875f*c5 - 8.75f*c3 + 1.875f*c);
    cb[6] = 1.0171072362820548f * (32.0f*c6 - 48.0f*c4 + 18.0f*c2 - 1.0f);

    float rb[6] = { ra.x, ra.y, rbp.x, rbp.y, rc.x, rc.y };

    int ji = id_ji[t];
    float* dst = g_sbf + (size_t)ji * SBF_STRIDE;
    #pragma unroll
    for (int q = 0; q < 10; q++) {
        int w = 4*q;
        float4 v = make_float4(cb[(w+0)/6] * rb[(w+0)%6],
                               cb[(w+1)/6] * rb[(w+1)%6],
                               cb[(w+2)/6] * rb[(w+2)%6],
                               cb[(w+3)/6] * rb[(w+3)%6]);
        atomicAdd((float4*)(dst + w), v);
    }
    atomicAdd((float2*)(dst + 40), make_float2(cb[6]*rb[4], cb[6]*rb[5]));
}

// ===========================================================================
// Kernel 3a: split W = [W_sbf; W_rbf] (48x128) into bf16 hi/lo planes, packed
// as bf16x2 along k (pair p covers k=2p, 2p+1).
// ===========================================================================
__global__ void pack_w_kernel(const float* __restrict__ W_sbf,
                              const float* __restrict__ W_rbf)
{
    int idx = blockIdx.x * blockDim.x + threadIdx.x;
    if (idx >= 24 * HID) return;
    int p = idx >> 7, h = idx & 127;
    int k0 = 2*p, k1 = 2*p + 1;
    float v0 = (k0 < 42) ? W_sbf[k0*HID + h] : W_rbf[(k0-42)*HID + h];
    float v1 = (k1 < 42) ? W_sbf[k1*HID + h] : W_rbf[(k1-42)*HID + h];
    __nv_bfloat16 h0 = __float2bfloat16_rn(v0);
    __nv_bfloat16 h1 = __float2bfloat16_rn(v1);
    __nv_bfloat16 l0 = __float2bfloat16_rn(v0 - __bfloat162float(h0));
    __nv_bfloat16 l1 = __float2bfloat16_rn(v1 - __bfloat162float(h1));
    __nv_bfloat162 ph; ph.x = h0; ph.y = h1;
    __nv_bfloat162 pl; pl.x = l0; pl.y = l1;
    g_Wp_hi[idx] = *(uint32_t*)&ph;
    g_Wp_lo[idx] = *(uint32_t*)&pl;
}

// ===========================================================================
// Kernel 3b: out = feat @ W + b via mma.sync m16n8k16 bf16 double-split
// (hi*hi + lo*hi + hi*lo, fp32 accumulators). Persistent single-wave grid.
// Depth-2 register prefetch (tile t+2G in flight during tile t) + double-
// buffered smem staging -> one __syncthreads per tile, 2x outstanding DRAM
// bytes vs depth-1.
// ===========================================================================
__device__ __forceinline__ void mma_bf16(float* d, const uint32_t* a,
                                         const uint32_t* b)
{
    asm volatile(
        "mma.sync.aligned.m16n8k16.row.col.f32.bf16.bf16.f32 "
        "{%0,%1,%2,%3}, {%4,%5,%6,%7}, {%8,%9}, {%0,%1,%2,%3};"
        : "+f"(d[0]), "+f"(d[1]), "+f"(d[2]), "+f"(d[3])
        : "r"(a[0]), "r"(a[1]), "r"(a[2]), "r"(a[3]), "r"(b[0]), "r"(b[1]));
}

__device__ __forceinline__ uint32_t split_pair(float v0, float v1, uint32_t* lo_out)
{
    __nv_bfloat16 h0 = __float2bfloat16_rn(v0);
    __nv_bfloat16 h1 = __float2bfloat16_rn(v1);
    __nv_bfloat16 l0 = __float2bfloat16_rn(v0 - __bfloat162float(h0));
    __nv_bfloat16 l1 = __float2bfloat16_rn(v1 - __bfloat162float(h1));
    __nv_bfloat162 ph; ph.x = h0; ph.y = h1;
    __nv_bfloat162 pl; pl.x = l0; pl.y = l1;
    *lo_out = *(uint32_t*)&pl;
    return *(uint32_t*)&ph;
}

__global__ void __launch_bounds__(256) out_mma(
    const float* __restrict__ b_rbf,
    float* __restrict__ out)
{
    __shared__ uint32_t Ahi[2][TILE_M * APAD];
    __shared__ uint32_t Alo[2][TILE_M * APAD];

    int tid = threadIdx.x, lane = tid & 31, warp = tid >> 5;
    int wm = warp & 1;         // m sub-tile (16 rows each)
    int wn = warp >> 1;        // n sub-tile (32 cols each), 0..3
    int g = lane >> 2, tig = lane & 3;

    // Resident B fragments: [kstep][n8-subtile][2], hi and lo planes.
    uint32_t bh[3][4][2], bl[3][4][2];
    #pragma unroll
    for (int ks = 0; ks < 3; ks++)
        #pragma unroll
        for (int s = 0; s < 4; s++) {
            int n = wn*32 + s*8 + g;
            bh[ks][s][0] = g_Wp_hi[(ks*8 + tig    )*HID + n];
            bh[ks][s][1] = g_Wp_hi[(ks*8 + tig + 4)*HID + n];
            bl[ks][s][0] = g_Wp_lo[(ks*8 + tig    )*HID + n];
            bl[ks][s][1] = g_Wp_lo[(ks*8 + tig + 4)*HID + n];
        }
    float bias[4][2];
    #pragma unroll
    for (int s = 0; s < 4; s++) {
        int n = wn*32 + s*8 + 2*tig;
        bias[s][0] = b_rbf[n];
        bias[s][1] = b_rbf[n+1];
    }

    int row_l = tid >> 3;     // 0..31: A-staging row
    int ch    = tid & 7;      // 0..7: 6-float chunk; ch 0..6 -> sbf, ch 7 -> rbf

    const int G = gridDim.x;

    // depth-2 prologue prefetch: tiles b and b+G
    float2 P[2][3];
    {
        int e = blockIdx.x * TILE_M + row_l;
        const float* fr = (ch < 7) ? g_sbf + (size_t)e * SBF_STRIDE + ch*6
                                   : g_rbf + (size_t)e * 6;
        P[0][0] = __ldg((const float2*)(fr + 0));
        P[0][1] = __ldg((const float2*)(fr + 2));
        P[0][2] = __ldg((const float2*)(fr + 4));
    }
    {
        int nt = blockIdx.x + G;
        if (nt < N_TILES) {
            int e = nt * TILE_M + row_l;
            const float* fr = (ch < 7) ? g_sbf + (size_t)e * SBF_STRIDE + ch*6
                                       : g_rbf + (size_t)e * 6;
            P[1][0] = __ldg((const float2*)(fr + 0));
            P[1][1] = __ldg((const float2*)(fr + 2));
            P[1][2] = __ldg((const float2*)(fr + 4));
        }
    }

    int k = 0;
    for (int tile = blockIdx.x; tile < N_TILES; tile += G, k ^= 1) {
        // ---- stage tile (loaded 2 iterations ago) into buffer k ----
        {
            uint32_t lo;
            int base = row_l * APAD + ch * 3;
            Ahi[k][base + 0] = split_pair(P[k][0].x, P[k][0].y, &lo); Alo[k][base + 0] = lo;
            Ahi[k][base + 1] = split_pair(P[k][1].x, P[k][1].y, &lo); Alo[k][base + 1] = lo;
            Ahi[k][base + 2] = split_pair(P[k][2].x, P[k][2].y, &lo); Alo[k][base + 2] = lo;
        }
        __syncthreads();   // single barrier per tile (double-buffered smem)

        // ---- prefetch tile + 2G into the register set just consumed ----
        int nt = tile + 2*G;
        if (nt < N_TILES) {
            int e = nt*TILE_M + row_l;
            const float* fr = (ch < 7) ? g_sbf + (size_t)e * SBF_STRIDE + ch*6
                                       : g_rbf + (size_t)e * 6;
            P[k][0] = __ldg((const float2*)(fr + 0));
            P[k][1] = __ldg((const float2*)(fr + 2));
            P[k][2] = __ldg((const float2*)(fr + 4));
        }

        // ---- compute ----
        float d[4][4];
        #pragma unroll
        for (int s = 0; s < 4; s++) {
            d[s][0] = bias[s][0]; d[s][1] = bias[s][1];
            d[s][2] = bias[s][0]; d[s][3] = bias[s][1];
        }
        int r0 = wm*16 + g;
        #pragma unroll
        for (int ks = 0; ks < 3; ks++) {
            uint32_t ah[4], al[4];
            int q0 = ks*8 + tig;
            ah[0] = Ahi[k][(r0    )*APAD + q0    ];  al[0] = Alo[k][(r0    )*APAD + q0    ];
            ah[1] = Ahi[k][(r0 + 8)*APAD + q0    ];  al[1] = Alo[k][(r0 + 8)*APAD + q0    ];
            ah[2] = Ahi[k][(r0    )*APAD + q0 + 4];  al[2] = Alo[k][(r0    )*APAD + q0 + 4];
            ah[3] = Ahi[k][(r0 + 8)*APAD + q0 + 4];  al[3] = Alo[k][(r0 + 8)*APAD + q0 + 4];
            #pragma unroll
            for (int s = 0; s < 4; s++) {
                mma_bf16(d[s], ah, bh[ks][s]);   // hi * hi
                mma_bf16(d[s], al, bh[ks][s]);   // lo * hi
                mma_bf16(d[s], ah, bl[ks][s]);   // hi * lo
            }
        }

        // ---- store (streaming; write-once 256MB) ----
        int mb = tile*TILE_M + wm*16;
        #pragma unroll
        for (int s = 0; s < 4; s++) {
            int n = wn*32 + s*8 + 2*tig;
            __stcs((float2*)(out + (size_t)(mb + g    )*HID + n),
                   make_float2(d[s][0], d[s][1]));
            __stcs((float2*)(out + (size_t)(mb + g + 8)*HID + n),
                   make_float2(d[s][2], d[s][3]));
        }
    }
}

// ===========================================================================
extern "C" void kernel_launch(void* const* d_in, const int* in_sizes, int n_in,
                              void* d_out, int out_size)
{
    const float* node_pos  = (const float*)d_in[0];
    const float* group_pos = (const float*)d_in[1];
    // d_in[2] = edge_attr (unused by reference)
    const float* W_rbf     = (const float*)d_in[3];
    const float* b_rbf     = (const float*)d_in[4];
    const float* W_sbf     = (const float*)d_in[5];
    const int*   edge_i    = (const int*)d_in[6];
    const int*   edge_j    = (const int*)d_in[7];
    const int*   trip_i    = (const int*)d_in[8];
    const int*   trip_j    = (const int*)d_in[9];
    const int*   trip_k    = (const int*)d_in[10];
    const int*   id_kj     = (const int*)d_in[11];
    const int*   id_ji     = (const int*)d_in[12];
    float* out = (float*)d_out;

    void* sbf_ptr = nullptr;
    cudaGetSymbolAddress(&sbf_ptr, g_sbf);
    cudaMemsetAsync(sbf_ptr, 0, (size_t)N_EDGES * SBF_STRIDE * sizeof(float), 0);

    pack_w_kernel<<<12, 256>>>(W_sbf, W_rbf);
    rbf_kernel<<<(N_EDGES + 255)/256, 256>>>(node_pos, edge_i, edge_j);
    triplet_kernel<<<(N_TRIP + 255)/256, 256>>>(node_pos, group_pos,
                                                trip_i, trip_j, trip_k,
                                                id_kj, id_ji);
    out_mma<<<296, 256>>>(b_rbf, out);
}

// round 14
// speedup vs baseline: 1.2151x; 1.2151x over previous
#include <cuda_runtime.h>
#include <cuda_bf16.h>
#include <math.h>
#include <stdint.h>

#define N_NODES   50000
#define N_GROUPS  10000
#define N_EDGES   500000
#define N_TRIP    1000000
#define HID       128
#define EPSF      1e-6f
#define CUTOFF    5.0f
#define PI_F      3.14159265358979323846f

#define SBF_STRIDE 44                  // 42 used + 2 pad -> 176B rows (16B aligned)
#define TILE_M    32
#define N_TILES   (N_EDGES / TILE_M)   // 15625 exact
#define APAD      25                   // smem A plane row stride (u32)

// sbf accumulators (zeroed by memset each call); compact rbf rows (12 MB, L2-resident)
__device__ __align__(16) float g_sbf[(size_t)N_EDGES * SBF_STRIDE];
__device__ __align__(16) float g_rbf[(size_t)N_EDGES * 6];
__device__ unsigned char g_active[N_EDGES];   // envelope-nonzero flag per edge
// W split planes, packed as bf16x2 pairs in B-fragment order: Wp[k/2][h]
__device__ uint32_t g_Wp_hi[24 * HID];
__device__ uint32_t g_Wp_lo[24 * HID];

// ===========================================================================
// Kernel 1: per-edge RBF -> compact g_rbf + active flag
// ===========================================================================
__global__ void rbf_kernel(const float* __restrict__ node_pos,
                           const int*   __restrict__ edge_i,
                           const int*   __restrict__ edge_j)
{
    int e = blockIdx.x * blockDim.x + threadIdx.x;
    if (e >= N_EDGES) return;
    int i = edge_i[e], j = edge_j[e];
    float dx = node_pos[3*i+0] - node_pos[3*j+0];
    float dy = node_pos[3*i+1] - node_pos[3*j+1];
    float dz = node_pos[3*i+2] - node_pos[3*j+2];
    float d  = sqrtf(dx*dx + dy*dy + dz*dz);
    d = fmaxf(d, EPSF);
    float ds = d / CUTOFF;

    float r0=0.f,r1=0.f,r2=0.f,r3=0.f,r4=0.f,r5=0.f;
    bool act = (ds <= 1.0f);
    if (act) {
        float th = PI_F * ds;
        float s, c;
        sincosf(th, &s, &c);
        float env = 0.5f * (c + 1.0f);
        float inv = env / fmaxf(ds, 1e-6f);
        float c2 = 2.0f * c;
        float sm2 = 0.0f, sm1 = s, sn;
        r0 = inv * sm1;
        sn = c2*sm1 - sm2; sm2 = sm1; sm1 = sn; r1 = inv * sn;
        sn = c2*sm1 - sm2; sm2 = sm1; sm1 = sn; r2 = inv * sn;
        sn = c2*sm1 - sm2; sm2 = sm1; sm1 = sn; r3 = inv * sn;
        sn = c2*sm1 - sm2; sm2 = sm1; sm1 = sn; r4 = inv * sn;
        sn = c2*sm1 - sm2; sm2 = sm1; sm1 = sn; r5 = inv * sn;
    }
    float* row = g_rbf + (size_t)e * 6;
    *(float2*)(row + 0) = make_float2(r0, r1);
    *(float2*)(row + 2) = make_float2(r2, r3);
    *(float2*)(row + 4) = make_float2(r4, r5);
    g_active[e] = act ? 1 : 0;
}

// ===========================================================================
// Kernel 2: triplet features. cos(theta) algebraically; 1-byte active-flag
// test first (flag==0 iff rbf row is exactly zero -> contribution exactly 0).
// ===========================================================================
__global__ void triplet_kernel(const float* __restrict__ node_pos,
                               const float* __restrict__ group_pos,
                               const int* __restrict__ t_i,
                               const int* __restrict__ t_j,
                               const int* __restrict__ t_k,
                               const int* __restrict__ id_kj,
                               const int* __restrict__ id_ji)
{
    int t = blockIdx.x * blockDim.x + threadIdx.x;
    if (t >= N_TRIP) return;

    int kj = id_kj[t];
    if (!__ldg(&g_active[kj])) return;

    const float* rrow = g_rbf + (size_t)kj * 6;
    float2 ra  = __ldg((const float2*)(rrow + 0));
    float2 rbp = __ldg((const float2*)(rrow + 2));
    float2 rc  = __ldg((const float2*)(rrow + 4));

    int ti = t_i[t], tj = t_j[t], tk = t_k[t];
    float gx = group_pos[3*ti+0], gy = group_pos[3*ti+1], gz = group_pos[3*ti+2];
    float ax = node_pos[3*tj+0] - gx, ay = node_pos[3*tj+1] - gy, az = node_pos[3*tj+2] - gz;
    float bx = node_pos[3*tk+0] - gx, by = node_pos[3*tk+1] - gy, bz = node_pos[3*tk+2] - gz;

    float n1 = sqrtf(ax*ax + ay*ay + az*az) + EPSF;
    float n2 = sqrtf(bx*bx + by*by + bz*bz) + EPSF;
    bool too_close = (n1 < 1e-4f) || (n2 < 1e-4f);
    float i1 = __fdividef(1.0f, n1), i2 = __fdividef(1.0f, n2);
    float ux = ax*i1, uy = ay*i1, uz = az*i1;
    float vx = bx*i2, vy = by*i2, vz = bz*i2;
    float x = ux*vx + uy*vy + uz*vz;
    x = fminf(fmaxf(x, -1.0f + EPSF), 1.0f - EPSF);
    float cx_ = uy*vz - uz*vy;
    float cy_ = uz*vx - ux*vz;
    float cz_ = ux*vy - uy*vx;
    float y2 = cx_*cx_ + cy_*cy_ + cz_*cz_;
    float c = too_close ? 0.0f : x * rsqrtf(x*x + y2);

    float c2 = c*c, c3 = c2*c, c4 = c2*c2, c5 = c3*c2, c6 = c3*c3;
    float cb[7];
    cb[0] = 0.2820947917738781f;
    cb[1] = 0.4886025119029199f * c;
    cb[2] = 0.6307831305050401f * (1.5f*c2 - 0.5f);
    cb[3] = 0.7463526651802308f * (2.5f*c3 - 1.5f*c);
    cb[4] = 0.8462843753216345f * (4.375f*c4 - 3.75f*c2 + 0.375f);
    cb[5] = 0.9356025796273889f * (7.875f*c5 - 8.75f*c3 + 1.875f*c);
    cb[6] = 1.0171072362820548f * (32.0f*c6 - 48.0f*c4 + 18.0f*c2 - 1.0f);

    float rb[6] = { ra.x, ra.y, rbp.x, rbp.y, rc.x, rc.y };

    int ji = id_ji[t];
    float* dst = g_sbf + (size_t)ji * SBF_STRIDE;
    #pragma unroll
    for (int q = 0; q < 10; q++) {
        int w = 4*q;
        float4 v = make_float4(cb[(w+0)/6] * rb[(w+0)%6],
                               cb[(w+1)/6] * rb[(w+1)%6],
                               cb[(w+2)/6] * rb[(w+2)%6],
                               cb[(w+3)/6] * rb[(w+3)%6]);
        atomicAdd((float4*)(dst + w), v);
    }
    atomicAdd((float2*)(dst + 40), make_float2(cb[6]*rb[4], cb[6]*rb[5]));
}

// ===========================================================================
// Kernel 3a: split W into bf16 hi/lo planes (bf16x2 packed along k)
// ===========================================================================
__global__ void pack_w_kernel(const float* __restrict__ W_sbf,
                              const float* __restrict__ W_rbf)
{
    int idx = blockIdx.x * blockDim.x + threadIdx.x;
    if (idx >= 24 * HID) return;
    int p = idx >> 7, h = idx & 127;
    int k0 = 2*p, k1 = 2*p + 1;
    float v0 = (k0 < 42) ? W_sbf[k0*HID + h] : W_rbf[(k0-42)*HID + h];
    float v1 = (k1 < 42) ? W_sbf[k1*HID + h] : W_rbf[(k1-42)*HID + h];
    __nv_bfloat16 h0 = __float2bfloat16_rn(v0);
    __nv_bfloat16 h1 = __float2bfloat16_rn(v1);
    __nv_bfloat16 l0 = __float2bfloat16_rn(v0 - __bfloat162float(h0));
    __nv_bfloat16 l1 = __float2bfloat16_rn(v1 - __bfloat162float(h1));
    __nv_bfloat162 ph; ph.x = h0; ph.y = h1;
    __nv_bfloat162 pl; pl.x = l0; pl.y = l1;
    g_Wp_hi[idx] = *(uint32_t*)&ph;
    g_Wp_lo[idx] = *(uint32_t*)&pl;
}

// ===========================================================================
// Kernel 3b: out = feat @ W + b via mma.sync m16n8k16 bf16 double-split.
// Persistent grid, loop unrolled x2 with DISTINCT named prefetch register
// sets (P0*, P1* — no dynamic indexing, stays in registers) and explicit
// double smem buffers. Depth-2 in-flight DRAM loads, one barrier per tile.
// ===========================================================================
__device__ __forceinline__ void mma_bf16(float* d, const uint32_t* a,
                                         const uint32_t* b)
{
    asm volatile(
        "mma.sync.aligned.m16n8k16.row.col.f32.bf16.bf16.f32 "
        "{%0,%1,%2,%3}, {%4,%5,%6,%7}, {%8,%9}, {%0,%1,%2,%3};"
        : "+f"(d[0]), "+f"(d[1]), "+f"(d[2]), "+f"(d[3])
        : "r"(a[0]), "r"(a[1]), "r"(a[2]), "r"(a[3]), "r"(b[0]), "r"(b[1]));
}

__device__ __forceinline__ uint32_t split_pair(float v0, float v1, uint32_t* lo_out)
{
    __nv_bfloat16 h0 = __float2bfloat16_rn(v0);
    __nv_bfloat16 h1 = __float2bfloat16_rn(v1);
    __nv_bfloat16 l0 = __float2bfloat16_rn(v0 - __bfloat162float(h0));
    __nv_bfloat16 l1 = __float2bfloat16_rn(v1 - __bfloat162float(h1));
    __nv_bfloat162 ph; ph.x = h0; ph.y = h1;
    __nv_bfloat162 pl; pl.x = l0; pl.y = l1;
    *lo_out = *(uint32_t*)&pl;
    return *(uint32_t*)&ph;
}

struct MmaCtx {
    uint32_t bh[3][4][2], bl[3][4][2];
    float bias[4][2];
};

__device__ __forceinline__ void compute_and_store(
    const uint32_t* Ahi, const uint32_t* Alo, const MmaCtx& cx,
    int tile, int wm, int wn, int g, int tig, float* __restrict__ out)
{
    float d[4][4];
    #pragma unroll
    for (int s = 0; s < 4; s++) {
        d[s][0] = cx.bias[s][0]; d[s][1] = cx.bias[s][1];
        d[s][2] = cx.bias[s][0]; d[s][3] = cx.bias[s][1];
    }
    int r0 = wm*16 + g;
    #pragma unroll
    for (int ks = 0; ks < 3; ks++) {
        uint32_t ah[4], al[4];
        int q0 = ks*8 + tig;
        ah[0] = Ahi[(r0    )*APAD + q0    ];  al[0] = Alo[(r0    )*APAD + q0    ];
        ah[1] = Ahi[(r0 + 8)*APAD + q0    ];  al[1] = Alo[(r0 + 8)*APAD + q0    ];
        ah[2] = Ahi[(r0    )*APAD + q0 + 4];  al[2] = Alo[(r0    )*APAD + q0 + 4];
        ah[3] = Ahi[(r0 + 8)*APAD + q0 + 4];  al[3] = Alo[(r0 + 8)*APAD + q0 + 4];
        #pragma unroll
        for (int s = 0; s < 4; s++) {
            mma_bf16(d[s], ah, cx.bh[ks][s]);   // hi * hi
            mma_bf16(d[s], al, cx.bh[ks][s]);   // lo * hi
            mma_bf16(d[s], ah, cx.bl[ks][s]);   // hi * lo
        }
    }
    int mb = tile*TILE_M + wm*16;
    #pragma unroll
    for (int s = 0; s < 4; s++) {
        int n = wn*32 + s*8 + 2*tig;
        __stcs((float2*)(out + (size_t)(mb + g    )*HID + n),
               make_float2(d[s][0], d[s][1]));
        __stcs((float2*)(out + (size_t)(mb + g + 8)*HID + n),
               make_float2(d[s][2], d[s][3]));
    }
}

#define FETCH3(P0v, P1v, P2v, tile_expr)                                        \
    do {                                                                        \
        int _e = (tile_expr)*TILE_M + row_l;                                    \
        const float* _fr = (ch < 7) ? g_sbf + (size_t)_e * SBF_STRIDE + ch*6    \
                                    : g_rbf + (size_t)_e * 6;                   \
        P0v = __ldg((const float2*)(_fr + 0));                                  \
        P1v = __ldg((const float2*)(_fr + 2));                                  \
        P2v = __ldg((const float2*)(_fr + 4));                                  \
    } while (0)

#define STAGE3(buf_hi, buf_lo, P0v, P1v, P2v)                                   \
    do {                                                                        \
        uint32_t _lo;                                                           \
        int _base = row_l * APAD + ch * 3;                                      \
        buf_hi[_base + 0] = split_pair(P0v.x, P0v.y, &_lo); buf_lo[_base + 0] = _lo; \
        buf_hi[_base + 1] = split_pair(P1v.x, P1v.y, &_lo); buf_lo[_base + 1] = _lo; \
        buf_hi[_base + 2] = split_pair(P2v.x, P2v.y, &_lo); buf_lo[_base + 2] = _lo; \
    } while (0)

__global__ void __launch_bounds__(256, 2) out_mma(
    const float* __restrict__ b_rbf,
    float* __restrict__ out)
{
    __shared__ uint32_t Ahi0[TILE_M * APAD], Alo0[TILE_M * APAD];
    __shared__ uint32_t Ahi1[TILE_M * APAD], Alo1[TILE_M * APAD];

    int tid = threadIdx.x, lane = tid & 31, warp = tid >> 5;
    int wm = warp & 1;         // m sub-tile (16 rows each)
    int wn = warp >> 1;        // n sub-tile (32 cols each), 0..3
    int g = lane >> 2, tig = lane & 3;

    MmaCtx cx;
    #pragma unroll
    for (int ks = 0; ks < 3; ks++)
        #pragma unroll
        for (int s = 0; s < 4; s++) {
            int n = wn*32 + s*8 + g;
            cx.bh[ks][s][0] = g_Wp_hi[(ks*8 + tig    )*HID + n];
            cx.bh[ks][s][1] = g_Wp_hi[(ks*8 + tig + 4)*HID + n];
            cx.bl[ks][s][0] = g_Wp_lo[(ks*8 + tig    )*HID + n];
            cx.bl[ks][s][1] = g_Wp_lo[(ks*8 + tig + 4)*HID + n];
        }
    #pragma unroll
    for (int s = 0; s < 4; s++) {
        int n = wn*32 + s*8 + 2*tig;
        cx.bias[s][0] = b_rbf[n];
        cx.bias[s][1] = b_rbf[n+1];
    }

    int row_l = tid >> 3;     // 0..31: A-staging row
    int ch    = tid & 7;      // 0..7: 6-float chunk; ch 0..6 -> sbf, ch 7 -> rbf

    const int G = gridDim.x;

    // depth-2 prologue: prefetch tiles b and b+G into distinct register sets
    float2 Pa0, Pa1, Pa2, Pb0, Pb1, Pb2;
    FETCH3(Pa0, Pa1, Pa2, blockIdx.x);
    if (blockIdx.x + G < N_TILES) FETCH3(Pb0, Pb1, Pb2, blockIdx.x + G);

    for (int tile = blockIdx.x; tile < N_TILES; tile += 2*G) {
        // ---- half A: tile (buffer 0, register set Pa) ----
        STAGE3(Ahi0, Alo0, Pa0, Pa1, Pa2);
        __syncthreads();
        if (tile + 2*G < N_TILES) FETCH3(Pa0, Pa1, Pa2, tile + 2*G);
        compute_and_store(Ahi0, Alo0, cx, tile, wm, wn, g, tig, out);

        // ---- half B: tile+G (buffer 1, register set Pb) ----
        int tB = tile + G;
        if (tB < N_TILES) {
            STAGE3(Ahi1, Alo1, Pb0, Pb1, Pb2);
            __syncthreads();
            if (tB + 2*G < N_TILES) FETCH3(Pb0, Pb1, Pb2, tB + 2*G);
            compute_and_store(Ahi1, Alo1, cx, tB, wm, wn, g, tig, out);
        }
    }
}

// ===========================================================================
extern "C" void kernel_launch(void* const* d_in, const int* in_sizes, int n_in,
                              void* d_out, int out_size)
{
    const float* node_pos  = (const float*)d_in[0];
    const float* group_pos = (const float*)d_in[1];
    // d_in[2] = edge_attr (unused by reference)
    const float* W_rbf     = (const float*)d_in[3];
    const float* b_rbf     = (const float*)d_in[4];
    const float* W_sbf     = (const float*)d_in[5];
    const int*   edge_i    = (const int*)d_in[6];
    const int*   edge_j    = (const int*)d_in[7];
    const int*   trip_i    = (const int*)d_in[8];
    const int*   trip_j    = (const int*)d_in[9];
    const int*   trip_k    = (const int*)d_in[10];
    const int*   id_kj     = (const int*)d_in[11];
    const int*   id_ji     = (const int*)d_in[12];
    float* out = (float*)d_out;

    void* sbf_ptr = nullptr;
    cudaGetSymbolAddress(&sbf_ptr, g_sbf);
    cudaMemsetAsync(sbf_ptr, 0, (size_t)N_EDGES * SBF_STRIDE * sizeof(float), 0);

    pack_w_kernel<<<12, 256>>>(W_sbf, W_rbf);
    rbf_kernel<<<(N_EDGES + 255)/256, 256>>>(node_pos, edge_i, edge_j);
    triplet_kernel<<<(N_TRIP + 255)/256, 256>>>(node_pos, group_pos,
                                                trip_i, trip_j, trip_k,
                                                id_kj, id_ji);
    out_mma<<<296, 256>>>(b_rbf, out);
}

// round 15
// speedup vs baseline: 1.2694x; 1.0447x over previous
#include <cuda_runtime.h>
#include <cuda_bf16.h>
#include <math.h>
#include <stdint.h>

#define N_NODES   50000
#define N_GROUPS  10000
#define N_EDGES   500000
#define N_TRIP    1000000
#define HID       128
#define EPSF      1e-6f
#define CUTOFF    5.0f
#define PI_F      3.14159265358979323846f

#define SBF_STRIDE 44                  // 42 used + 2 pad -> 176B rows (16B aligned)
#define TILE_M    32
#define N_TILES   (N_EDGES / TILE_M)   // 15625 exact
#define APAD      28                   // smem A row stride (u32); 112B = 16B-mult for ldmatrix

// sbf accumulators (zeroed by memset each call); compact rbf rows (12 MB, L2-resident)
__device__ __align__(16) float g_sbf[(size_t)N_EDGES * SBF_STRIDE];
__device__ __align__(16) float g_rbf[(size_t)N_EDGES * 6];
__device__ unsigned char g_active[N_EDGES];   // envelope-nonzero flag per edge
// W split planes, packed as bf16x2 pairs in B-fragment order: Wp[k/2][h]
__device__ uint32_t g_Wp_hi[24 * HID];
__device__ uint32_t g_Wp_lo[24 * HID];

// ===========================================================================
// Kernel 1: per-edge RBF -> compact g_rbf + active flag
// ===========================================================================
__global__ void rbf_kernel(const float* __restrict__ node_pos,
                           const int*   __restrict__ edge_i,
                           const int*   __restrict__ edge_j)
{
    int e = blockIdx.x * blockDim.x + threadIdx.x;
    if (e >= N_EDGES) return;
    int i = edge_i[e], j = edge_j[e];
    float dx = node_pos[3*i+0] - node_pos[3*j+0];
    float dy = node_pos[3*i+1] - node_pos[3*j+1];
    float dz = node_pos[3*i+2] - node_pos[3*j+2];
    float d  = sqrtf(dx*dx + dy*dy + dz*dz);
    d = fmaxf(d, EPSF);
    float ds = d / CUTOFF;

    float r0=0.f,r1=0.f,r2=0.f,r3=0.f,r4=0.f,r5=0.f;
    bool act = (ds <= 1.0f);
    if (act) {
        float th = PI_F * ds;
        float s, c;
        sincosf(th, &s, &c);
        float env = 0.5f * (c + 1.0f);
        float inv = env / fmaxf(ds, 1e-6f);
        float c2 = 2.0f * c;
        float sm2 = 0.0f, sm1 = s, sn;
        r0 = inv * sm1;
        sn = c2*sm1 - sm2; sm2 = sm1; sm1 = sn; r1 = inv * sn;
        sn = c2*sm1 - sm2; sm2 = sm1; sm1 = sn; r2 = inv * sn;
        sn = c2*sm1 - sm2; sm2 = sm1; sm1 = sn; r3 = inv * sn;
        sn = c2*sm1 - sm2; sm2 = sm1; sm1 = sn; r4 = inv * sn;
        sn = c2*sm1 - sm2; sm2 = sm1; sm1 = sn; r5 = inv * sn;
    }
    float* row = g_rbf + (size_t)e * 6;
    *(float2*)(row + 0) = make_float2(r0, r1);
    *(float2*)(row + 2) = make_float2(r2, r3);
    *(float2*)(row + 4) = make_float2(r4, r5);
    g_active[e] = act ? 1 : 0;
}

// ===========================================================================
// Kernel 2: triplet features. cos(theta) algebraically; 1-byte active-flag
// test first (flag==0 iff rbf row is exactly zero -> contribution exactly 0).
// ===========================================================================
__global__ void triplet_kernel(const float* __restrict__ node_pos,
                               const float* __restrict__ group_pos,
                               const int* __restrict__ t_i,
                               const int* __restrict__ t_j,
                               const int* __restrict__ t_k,
                               const int* __restrict__ id_kj,
                               const int* __restrict__ id_ji)
{
    int t = blockIdx.x * blockDim.x + threadIdx.x;
    if (t >= N_TRIP) return;

    int kj = id_kj[t];
    if (!__ldg(&g_active[kj])) return;

    const float* rrow = g_rbf + (size_t)kj * 6;
    float2 ra  = __ldg((const float2*)(rrow + 0));
    float2 rbp = __ldg((const float2*)(rrow + 2));
    float2 rc  = __ldg((const float2*)(rrow + 4));

    int ti = t_i[t], tj = t_j[t], tk = t_k[t];
    float gx = group_pos[3*ti+0], gy = group_pos[3*ti+1], gz = group_pos[3*ti+2];
    float ax = node_pos[3*tj+0] - gx, ay = node_pos[3*tj+1] - gy, az = node_pos[3*tj+2] - gz;
    float bx = node_pos[3*tk+0] - gx, by = node_pos[3*tk+1] - gy, bz = node_pos[3*tk+2] - gz;

    float n1 = sqrtf(ax*ax + ay*ay + az*az) + EPSF;
    float n2 = sqrtf(bx*bx + by*by + bz*bz) + EPSF;
    bool too_close = (n1 < 1e-4f) || (n2 < 1e-4f);
    float i1 = __fdividef(1.0f, n1), i2 = __fdividef(1.0f, n2);
    float ux = ax*i1, uy = ay*i1, uz = az*i1;
    float vx = bx*i2, vy = by*i2, vz = bz*i2;
    float x = ux*vx + uy*vy + uz*vz;
    x = fminf(fmaxf(x, -1.0f + EPSF), 1.0f - EPSF);
    float cx_ = uy*vz - uz*vy;
    float cy_ = uz*vx - ux*vz;
    float cz_ = ux*vy - uy*vx;
    float y2 = cx_*cx_ + cy_*cy_ + cz_*cz_;
    float c = too_close ? 0.0f : x * rsqrtf(x*x + y2);

    float c2 = c*c, c3 = c2*c, c4 = c2*c2, c5 = c3*c2, c6 = c3*c3;
    float cb[7];
    cb[0] = 0.2820947917738781f;
    cb[1] = 0.4886025119029199f * c;
    cb[2] = 0.6307831305050401f * (1.5f*c2 - 0.5f);
    cb[3] = 0.7463526651802308f * (2.5f*c3 - 1.5f*c);
    cb[4] = 0.8462843753216345f * (4.375f*c4 - 3.75f*c2 + 0.375f);
    cb[5] = 0.9356025796273889f * (7.875f*c5 - 8.75f*c3 + 1.875f*c);
    cb[6] = 1.0171072362820548f * (32.0f*c6 - 48.0f*c4 + 18.0f*c2 - 1.0f);

    float rb[6] = { ra.x, ra.y, rbp.x, rbp.y, rc.x, rc.y };

    int ji = id_ji[t];
    float* dst = g_sbf + (size_t)ji * SBF_STRIDE;
    #pragma unroll
    for (int q = 0; q < 10; q++) {
        int w = 4*q;
        float4 v = make_float4(cb[(w+0)/6] * rb[(w+0)%6],
                               cb[(w+1)/6] * rb[(w+1)%6],
                               cb[(w+2)/6] * rb[(w+2)%6],
                               cb[(w+3)/6] * rb[(w+3)%6]);
        atomicAdd((float4*)(dst + w), v);
    }
    atomicAdd((float2*)(dst + 40), make_float2(cb[6]*rb[4], cb[6]*rb[5]));
}

// ===========================================================================
// Kernel 3a: split W into bf16 hi/lo planes (bf16x2 packed along k)
// ===========================================================================
__global__ void pack_w_kernel(const float* __restrict__ W_sbf,
                              const float* __restrict__ W_rbf)
{
    int idx = blockIdx.x * blockDim.x + threadIdx.x;
    if (idx >= 24 * HID) return;
    int p = idx >> 7, h = idx & 127;
    int k0 = 2*p, k1 = 2*p + 1;
    float v0 = (k0 < 42) ? W_sbf[k0*HID + h] : W_rbf[(k0-42)*HID + h];
    float v1 = (k1 < 42) ? W_sbf[k1*HID + h] : W_rbf[(k1-42)*HID + h];
    __nv_bfloat16 h0 = __float2bfloat16_rn(v0);
    __nv_bfloat16 h1 = __float2bfloat16_rn(v1);
    __nv_bfloat16 l0 = __float2bfloat16_rn(v0 - __bfloat162float(h0));
    __nv_bfloat16 l1 = __float2bfloat16_rn(v1 - __bfloat162float(h1));
    __nv_bfloat162 ph; ph.x = h0; ph.y = h1;
    __nv_bfloat162 pl; pl.x = l0; pl.y = l1;
    g_Wp_hi[idx] = *(uint32_t*)&ph;
    g_Wp_lo[idx] = *(uint32_t*)&pl;
}

// ===========================================================================
// Kernel 3b: out = feat @ W + b via mma.sync m16n8k16 bf16 double-split.
// A fragments loaded with ldmatrix.m8n8.x4 (one LDSM per (ks,plane) instead
// of 8 scalar LDS) -> ~8x fewer L1 fragment wavefronts. Depth-2 register
// prefetch + double-buffered smem (named register sets, no dynamic indexing).
// ===========================================================================
__device__ __forceinline__ void mma_bf16(float* d, const uint32_t* a,
                                         const uint32_t* b)
{
    asm volatile(
        "mma.sync.aligned.m16n8k16.row.col.f32.bf16.bf16.f32 "
        "{%0,%1,%2,%3}, {%4,%5,%6,%7}, {%8,%9}, {%0,%1,%2,%3};"
        : "+f"(d[0]), "+f"(d[1]), "+f"(d[2]), "+f"(d[3])
        : "r"(a[0]), "r"(a[1]), "r"(a[2]), "r"(a[3]), "r"(b[0]), "r"(b[1]));
}

__device__ __forceinline__ void ldsm_x4(uint32_t* r, uint32_t addr)
{
    asm volatile("ldmatrix.sync.aligned.m8n8.x4.shared.b16 {%0,%1,%2,%3}, [%4];"
                 : "=r"(r[0]), "=r"(r[1]), "=r"(r[2]), "=r"(r[3]) : "r"(addr));
}

__device__ __forceinline__ uint32_t split_pair(float v0, float v1, uint32_t* lo_out)
{
    __nv_bfloat16 h0 = __float2bfloat16_rn(v0);
    __nv_bfloat16 h1 = __float2bfloat16_rn(v1);
    __nv_bfloat16 l0 = __float2bfloat16_rn(v0 - __bfloat162float(h0));
    __nv_bfloat16 l1 = __float2bfloat16_rn(v1 - __bfloat162float(h1));
    __nv_bfloat162 ph; ph.x = h0; ph.y = h1;
    __nv_bfloat162 pl; pl.x = l0; pl.y = l1;
    *lo_out = *(uint32_t*)&pl;
    return *(uint32_t*)&ph;
}

struct MmaCtx {
    uint32_t bh[3][4][2], bl[3][4][2];
    float bias[4][2];
};

// ldmatrix lane-address offset within an A plane (bytes), per (lane, wm):
//   matrix i = lane>>3 (M0,M1 = row halves of low k-half; M2,M3 = high),
//   row within matrix = lane&7.
__device__ __forceinline__ uint32_t ldsm_lane_off(int lane, int wm)
{
    int i = lane >> 3, r = lane & 7;
    int row = wm*16 + (i & 1)*8 + r;
    int colw = (i >> 1) * 4;           // word offset within k-half group
    return (uint32_t)((row * APAD + colw) * 4);
}

__device__ __forceinline__ void compute_and_store(
    uint32_t hi_base, uint32_t lo_base, uint32_t lane_off, const MmaCtx& cx,
    int tile, int wm, int wn, int g, int tig, float* __restrict__ out)
{
    float d[4][4];
    #pragma unroll
    for (int s = 0; s < 4; s++) {
        d[s][0] = cx.bias[s][0]; d[s][1] = cx.bias[s][1];
        d[s][2] = cx.bias[s][0]; d[s][3] = cx.bias[s][1];
    }
    #pragma unroll
    for (int ks = 0; ks < 3; ks++) {
        uint32_t ah[4], al[4];
        ldsm_x4(ah, hi_base + lane_off + ks*32);   // ks*8 words = 32 bytes
        ldsm_x4(al, lo_base + lane_off + ks*32);
        #pragma unroll
        for (int s = 0; s < 4; s++) {
            mma_bf16(d[s], ah, cx.bh[ks][s]);   // hi * hi
            mma_bf16(d[s], al, cx.bh[ks][s]);   // lo * hi
            mma_bf16(d[s], ah, cx.bl[ks][s]);   // hi * lo
        }
    }
    int mb = tile*TILE_M + wm*16;
    #pragma unroll
    for (int s = 0; s < 4; s++) {
        int n = wn*32 + s*8 + 2*tig;
        __stcs((float2*)(out + (size_t)(mb + g    )*HID + n),
               make_float2(d[s][0], d[s][1]));
        __stcs((float2*)(out + (size_t)(mb + g + 8)*HID + n),
               make_float2(d[s][2], d[s][3]));
    }
}

#define FETCH3(P0v, P1v, P2v, tile_expr)                                        \
    do {                                                                        \
        int _e = (tile_expr)*TILE_M + row_l;                                    \
        const float* _fr = (ch < 7) ? g_sbf + (size_t)_e * SBF_STRIDE + ch*6    \
                                    : g_rbf + (size_t)_e * 6;                   \
        P0v = __ldg((const float2*)(_fr + 0));                                  \
        P1v = __ldg((const float2*)(_fr + 2));                                  \
        P2v = __ldg((const float2*)(_fr + 4));                                  \
    } while (0)

#define STAGE3(buf_hi, buf_lo, P0v, P1v, P2v)                                   \
    do {                                                                        \
        uint32_t _lo;                                                           \
        int _base = row_l * APAD + ch * 3;                                      \
        buf_hi[_base + 0] = split_pair(P0v.x, P0v.y, &_lo); buf_lo[_base + 0] = _lo; \
        buf_hi[_base + 1] = split_pair(P1v.x, P1v.y, &_lo); buf_lo[_base + 1] = _lo; \
        buf_hi[_base + 2] = split_pair(P2v.x, P2v.y, &_lo); buf_lo[_base + 2] = _lo; \
    } while (0)

__global__ void __launch_bounds__(256, 2) out_mma(
    const float* __restrict__ b_rbf,
    float* __restrict__ out)
{
    __shared__ __align__(16) uint32_t Ahi0[TILE_M * APAD], Alo0[TILE_M * APAD];
    __shared__ __align__(16) uint32_t Ahi1[TILE_M * APAD], Alo1[TILE_M * APAD];

    int tid = threadIdx.x, lane = tid & 31, warp = tid >> 5;
    int wm = warp & 1;         // m sub-tile (16 rows each)
    int wn = warp >> 1;        // n sub-tile (32 cols each), 0..3
    int g = lane >> 2, tig = lane & 3;

    MmaCtx cx;
    #pragma unroll
    for (int ks = 0; ks < 3; ks++)
        #pragma unroll
        for (int s = 0; s < 4; s++) {
            int n = wn*32 + s*8 + g;
            cx.bh[ks][s][0] = g_Wp_hi[(ks*8 + tig    )*HID + n];
            cx.bh[ks][s][1] = g_Wp_hi[(ks*8 + tig + 4)*HID + n];
            cx.bl[ks][s][0] = g_Wp_lo[(ks*8 + tig    )*HID + n];
            cx.bl[ks][s][1] = g_Wp_lo[(ks*8 + tig + 4)*HID + n];
        }
    #pragma unroll
    for (int s = 0; s < 4; s++) {
        int n = wn*32 + s*8 + 2*tig;
        cx.bias[s][0] = b_rbf[n];
        cx.bias[s][1] = b_rbf[n+1];
    }

    int row_l = tid >> 3;     // 0..31: A-staging row
    int ch    = tid & 7;      // 0..7: 6-float chunk; ch 0..6 -> sbf, ch 7 -> rbf

    uint32_t hi0 = (uint32_t)__cvta_generic_to_shared(Ahi0);
    uint32_t lo0 = (uint32_t)__cvta_generic_to_shared(Alo0);
    uint32_t hi1 = (uint32_t)__cvta_generic_to_shared(Ahi1);
    uint32_t lo1 = (uint32_t)__cvta_generic_to_shared(Alo1);
    uint32_t lane_off = ldsm_lane_off(lane, wm);

    const int G = gridDim.x;

    // depth-2 prologue: prefetch tiles b and b+G into distinct register sets
    float2 Pa0, Pa1, Pa2, Pb0, Pb1, Pb2;
    FETCH3(Pa0, Pa1, Pa2, blockIdx.x);
    if (blockIdx.x + G < N_TILES) FETCH3(Pb0, Pb1, Pb2, blockIdx.x + G);

    for (int tile = blockIdx.x; tile < N_TILES; tile += 2*G) {
        // ---- half A: tile (buffer 0, register set Pa) ----
        STAGE3(Ahi0, Alo0, Pa0, Pa1, Pa2);
        __syncthreads();
        if (tile + 2*G < N_TILES) FETCH3(Pa0, Pa1, Pa2, tile + 2*G);
        compute_and_store(hi0, lo0, lane_off, cx, tile, wm, wn, g, tig, out);

        // ---- half B: tile+G (buffer 1, register set Pb) ----
        int tB = tile + G;
        if (tB < N_TILES) {
            STAGE3(Ahi1, Alo1, Pb0, Pb1, Pb2);
            __syncthreads();
            if (tB + 2*G < N_TILES) FETCH3(Pb0, Pb1, Pb2, tB + 2*G);
            compute_and_store(hi1, lo1, lane_off, cx, tB, wm, wn, g, tig, out);
        }
    }
}

// ===========================================================================
extern "C" void kernel_launch(void* const* d_in, const int* in_sizes, int n_in,
                              void* d_out, int out_size)
{
    const float* node_pos  = (const float*)d_in[0];
    const float* group_pos = (const float*)d_in[1];
    // d_in[2] = edge_attr (unused by reference)
    const float* W_rbf     = (const float*)d_in[3];
    const float* b_rbf     = (const float*)d_in[4];
    const float* W_sbf     = (const float*)d_in[5];
    const int*   edge_i    = (const int*)d_in[6];
    const int*   edge_j    = (const int*)d_in[7];
    const int*   trip_i    = (const int*)d_in[8];
    const int*   trip_j    = (const int*)d_in[9];
    const int*   trip_k    = (const int*)d_in[10];
    const int*   id_kj     = (const int*)d_in[11];
    const int*   id_ji     = (const int*)d_in[12];
    float* out = (float*)d_out;

    void* sbf_ptr = nullptr;
    cudaGetSymbolAddress(&sbf_ptr, g_sbf);
    cudaMemsetAsync(sbf_ptr, 0, (size_t)N_EDGES * SBF_STRIDE * sizeof(float), 0);

    pack_w_kernel<<<12, 256>>>(W_sbf, W_rbf);
    rbf_kernel<<<(N_EDGES + 255)/256, 256>>>(node_pos, edge_i, edge_j);
    triplet_kernel<<<(N_TRIP + 255)/256, 256>>>(node_pos, group_pos,
                                                trip_i, trip_j, trip_k,
                                                id_kj, id_ji);
    out_mma<<<296, 256>>>(b_rbf, out);
}